// round 7
// baseline (speedup 1.0000x reference)
#include <cuda_runtime.h>
#include <cuda_bf16.h>
#include <cstdint>
#include <math.h>

#define EMBED 1024
#define HEADS 16
#define HDIM  64
#define BATCH 2
#define SEQ   2048
#define MTOT  (BATCH*SEQ)   // 4096
#define KCAT  3072          // 3*EMBED (split-bf16 concat)
#define KATT  192           // 3*HDIM  (split concat for attention)

// ---------------- scratch (device globals; no allocation allowed) ----------
__device__ float g_WeffQ[EMBED*EMBED];
__device__ float g_WeffK[EMBED*EMBED];
__device__ float g_beffQ[EMBED];
__device__ float g_beffK[EMBED];
__device__ __align__(256) __nv_bfloat16 g_Xcat[MTOT*KCAT];      // [m][3072] = [Xh|Xh|Xl]
__device__ __align__(256) __nv_bfloat16 g_WcatQ[EMBED*KCAT];    // [n][3072] = [Wh|Wl|Wh]
__device__ __align__(256) __nv_bfloat16 g_WcatK[EMBED*KCAT];
__device__ __align__(256) __nv_bfloat16 g_WcatV[EMBED*KCAT];
__device__ float g_v[MTOT*EMBED];   // [hb][n][d]
__device__ __align__(256) __nv_bfloat16 g_Qc[32*SEQ*KATT];      // [hb][n][192] = [Qh|Qh|Ql]*0.125
__device__ __align__(256) __nv_bfloat16 g_Kc[32*SEQ*KATT];      // [hb][n][192] = [Kh|Kl|Kh]
__device__ __align__(256) __nv_bfloat16 g_Vc[32*32*HDIM*KATT];  // [hb][tile][d][192]=[Vh|Vl|Vh] keys

// ======================= PTX helpers (sm_80-level) =========================
__device__ __forceinline__ uint32_t smem_u32(const void* p) {
    uint32_t a;
    asm("{ .reg .u64 t; cvta.to.shared.u64 t, %1; cvt.u32.u64 %0, t; }" : "=r"(a) : "l"(p));
    return a;
}
__device__ __forceinline__ void cp16(uint32_t s, const void* g) {
    asm volatile("cp.async.cg.shared.global [%0], [%1], 16;" :: "r"(s), "l"(g));
}
#define CP_COMMIT() asm volatile("cp.async.commit_group;" ::: "memory")
#define CP_WAIT1()  asm volatile("cp.async.wait_group 1;" ::: "memory")
#define CP_WAIT0()  asm volatile("cp.async.wait_group 0;" ::: "memory")

__device__ __forceinline__ void mma16816(float* c, const uint32_t* a, uint32_t b0, uint32_t b1) {
    asm volatile("mma.sync.aligned.m16n8k16.row.col.f32.bf16.bf16.f32 "
        "{%0,%1,%2,%3}, {%4,%5,%6,%7}, {%8,%9}, {%0,%1,%2,%3};"
        : "+f"(c[0]), "+f"(c[1]), "+f"(c[2]), "+f"(c[3])
        : "r"(a[0]), "r"(a[1]), "r"(a[2]), "r"(a[3]), "r"(b0), "r"(b1));
}
__device__ __forceinline__ void ldm4(uint32_t* r, uint32_t addr) {
    asm volatile("ldmatrix.sync.aligned.m8n8.x4.shared.b16 {%0,%1,%2,%3}, [%4];"
        : "=r"(r[0]), "=r"(r[1]), "=r"(r[2]), "=r"(r[3]) : "r"(addr));
}
__device__ __forceinline__ uint32_t packbf2(__nv_bfloat16 lo, __nv_bfloat16 hi) {
    __nv_bfloat162 t; t.x = lo; t.y = hi;
    return *(uint32_t*)&t;
}

// ---------------------------------------------------------------------------
// Fold per-head Wp into Wq / Wk (and biases).
// ---------------------------------------------------------------------------
__global__ void build_eff(const float* __restrict__ Wq, const float* __restrict__ bq,
                          const float* __restrict__ Wk, const float* __restrict__ bk,
                          const float* __restrict__ Wp)
{
    __shared__ float WpS[64*64];
    int i = threadIdx.x;
    for (int t = i; t < 64*64; t += 64) WpS[t] = Wp[t];
    __syncthreads();

    int h = blockIdx.y;
    int e = blockIdx.x;
    const float* W    = blockIdx.z ? Wk      : Wq;
    const float* b    = blockIdx.z ? bk      : bq;
    float*       Weff = blockIdx.z ? g_WeffK : g_WeffQ;
    float*       beff = blockIdx.z ? g_beffK : g_beffQ;

    float acc = 0.f;
    if (e < EMBED) {
        const float* src = W + e*EMBED + h*HDIM;
        #pragma unroll 8
        for (int d = 0; d < 64; d++) acc = fmaf(src[d], WpS[d*64 + i], acc);
        Weff[e*EMBED + h*HDIM + i] = acc;
    } else {
        const float* src = b + h*HDIM;
        #pragma unroll 8
        for (int d = 0; d < 64; d++) acc = fmaf(src[d], WpS[d*64 + i], acc);
        beff[h*HDIM + i] = acc;
    }
}

// ---------------------------------------------------------------------------
// X -> split-bf16 K-concat:  Xcat[m] = [hi(X) | hi(X) | lo(X)]
// ---------------------------------------------------------------------------
__global__ void convert_X(const float* __restrict__ x)
{
    int t = blockIdx.x*256 + threadIdx.x;
    float2 v = ((const float2*)x)[t];
    int m = t >> 9;
    int e = (t & 511) << 1;
    __nv_bfloat16 hx = __float2bfloat16(v.x), hy = __float2bfloat16(v.y);
    __nv_bfloat16 lx = __float2bfloat16(v.x - __bfloat162float(hx));
    __nv_bfloat16 ly = __float2bfloat16(v.y - __bfloat162float(hy));
    __nv_bfloat162 hi; hi.x = hx; hi.y = hy;
    __nv_bfloat162 lo; lo.x = lx; lo.y = ly;
    size_t base = (size_t)m*KCAT + e;
    *(__nv_bfloat162*)&g_Xcat[base        ] = hi;
    *(__nv_bfloat162*)&g_Xcat[base + 1024 ] = hi;
    *(__nv_bfloat162*)&g_Xcat[base + 2048 ] = lo;
}

// ---------------------------------------------------------------------------
// W (fp32 [k][n]) -> transposed split-bf16:  Wcat[n] = [hi | lo | hi]
// ---------------------------------------------------------------------------
__global__ void convert_W(const float* __restrict__ Wv)
{
    __shared__ float tile[32][33];
    int z = blockIdx.z;
    const float* src = (z == 0) ? g_WeffQ : (z == 1) ? g_WeffK : Wv;
    __nv_bfloat16* dst = (z == 0) ? g_WcatQ : (z == 1) ? g_WcatK : g_WcatV;
    int k0 = blockIdx.y*32, n0 = blockIdx.x*32;
    int tx = threadIdx.x, ty = threadIdx.y;
    #pragma unroll
    for (int j = 0; j < 32; j += 8)
        tile[ty+j][tx] = src[(size_t)(k0+ty+j)*EMBED + n0 + tx];
    __syncthreads();
    #pragma unroll
    for (int j = 0; j < 32; j += 8) {
        int n = ty + j;
        float v = tile[tx][n];
        __nv_bfloat16 hi = __float2bfloat16(v);
        __nv_bfloat16 lo = __float2bfloat16(v - __bfloat162float(hi));
        size_t base = (size_t)(n0+n)*KCAT + k0 + tx;
        dst[base       ] = hi;
        dst[base + 1024] = lo;
        dst[base + 2048] = hi;
    }
}

// ---------------------------------------------------------------------------
// Fused QKV HMMA GEMM, 3-stage cp.async pipeline.
// grid (32, 24): by>>3 selects Q/K/V; n0 = (by&7)*128. Block 128x128, 8 warps.
// Q/K epilogues write split-bf16 attention operands directly; V writes fp32.
// ---------------------------------------------------------------------------
#define GSTAGE 32768
#define NSTAGE 3
#define SMEM_GEMM (NSTAGE*GSTAGE)
#define NCHUNK (KCAT/64)   // 48

__device__ __forceinline__ void gemm_load(const __nv_bfloat16* A, const __nv_bfloat16* Bw,
                                          uint32_t sb, int stage, int m0, int n0,
                                          int chunk, int tid)
{
    uint32_t as = sb + stage*GSTAGE;
    uint32_t bs = as + 16384;
    const char* Ac = (const char*)A;
    const char* Bc = (const char*)Bw;
    #pragma unroll
    for (int r = 0; r < 4; r++) {
        int idx = tid + r*256;
        int row = idx >> 3, sec = idx & 7;
        cp16(as + row*128 + (((sec ^ (row & 7))) << 4),
             Ac + ((size_t)(m0+row)*KCAT + chunk*64 + sec*8)*2);
    }
    #pragma unroll
    for (int r = 0; r < 4; r++) {
        int idx = tid + r*256;
        int row = idx >> 3, sec = idx & 7;
        cp16(bs + row*128 + (((sec ^ (row & 7))) << 4),
             Bc + ((size_t)(n0+row)*KCAT + chunk*64 + sec*8)*2);
    }
}

__global__ __launch_bounds__(256) void gemm_fused(const float* __restrict__ bv)
{
    extern __shared__ char smem[];
    uint32_t sb = smem_u32(smem);
    int tid = threadIdx.x, wid = tid >> 5, l = tid & 31;
    int by = blockIdx.y;
    int which = by >> 3;                  // 0=Q, 1=K, 2=V
    int m0 = blockIdx.x * 128, n0 = (by & 7) * 128;
    int wm = (wid & 3) * 32, wn = (wid >> 2) * 64;

    const __nv_bfloat16* Bw = (which == 0) ? g_WcatQ : (which == 1) ? g_WcatK : g_WcatV;

    float c[2][8][4];
    #pragma unroll
    for (int mi = 0; mi < 2; mi++)
        #pragma unroll
        for (int j = 0; j < 8; j++)
            #pragma unroll
            for (int e = 0; e < 4; e++) c[mi][j][e] = 0.f;

    gemm_load(g_Xcat, Bw, sb, 0, m0, n0, 0, tid);
    CP_COMMIT();
    gemm_load(g_Xcat, Bw, sb, 1, m0, n0, 1, tid);
    CP_COMMIT();

    for (int i = 0; i < NCHUNK; i++) {
        if (i + 1 < NCHUNK) { CP_WAIT1(); } else { CP_WAIT0(); }
        __syncthreads();
        if (i + 2 < NCHUNK) {
            gemm_load(g_Xcat, Bw, sb, (i+2) % NSTAGE, m0, n0, i+2, tid);
            CP_COMMIT();
        }

        uint32_t as = sb + (i % NSTAGE)*GSTAGE;
        uint32_t bs = as + 16384;
        #pragma unroll
        for (int kk = 0; kk < 4; kk++) {
            uint32_t a0[4], a1[4];
            {
                int row = wm + (l & 15);
                int sec = 2*kk + (l >> 4);
                ldm4(a0, as + row*128 + ((sec ^ (row & 7)) << 4));
                row += 16;
                ldm4(a1, as + row*128 + ((sec ^ (row & 7)) << 4));
            }
            #pragma unroll
            for (int jp = 0; jp < 4; jp++) {
                uint32_t b[4];
                int row = wn + jp*16 + (l & 7) + ((l >> 4) << 3);
                int sec = 2*kk + ((l >> 3) & 1);
                ldm4(b, bs + row*128 + ((sec ^ (row & 7)) << 4));
                mma16816(c[0][2*jp],   a0, b[0], b[1]);
                mma16816(c[0][2*jp+1], a0, b[2], b[3]);
                mma16816(c[1][2*jp],   a1, b[0], b[1]);
                mma16816(c[1][2*jp+1], a1, b[2], b[3]);
            }
        }
    }

    // ---- epilogue ----
    if (which == 2) {
        // V: fp32 [hb][n][d]
        #pragma unroll
        for (int mi = 0; mi < 2; mi++) {
            int mbase = m0 + wm + mi*16 + (l >> 2);
            #pragma unroll
            for (int j = 0; j < 8; j++) {
                int ncol = n0 + wn + j*8 + (l & 3)*2;
                float2 bb = *(const float2*)&bv[ncol];
                int h = ncol >> 6, d = ncol & 63;
                #pragma unroll
                for (int half = 0; half < 2; half++) {
                    int m = mbase + half*8;
                    int b_ = m >> 11, ns = m & (SEQ-1);
                    float2 o;
                    o.x = c[mi][j][2*half+0] + bb.x;
                    o.y = c[mi][j][2*half+1] + bb.y;
                    *(float2*)&g_v[((size_t)(b_*HEADS + h)*SEQ + ns)*HDIM + d] = o;
                }
            }
        }
    } else {
        // Q/K: split-bf16 concat written directly
        const float* be = (which == 0) ? g_beffQ : g_beffK;
        __nv_bfloat16* dc = (which == 0) ? g_Qc : g_Kc;
        float scale = (which == 0) ? 0.125f : 1.0f;
        #pragma unroll
        for (int mi = 0; mi < 2; mi++) {
            int mbase = m0 + wm + mi*16 + (l >> 2);
            #pragma unroll
            for (int j = 0; j < 8; j++) {
                int ncol = n0 + wn + j*8 + (l & 3)*2;
                float2 bb = *(const float2*)&be[ncol];
                int h = ncol >> 6, d = ncol & 63;
                #pragma unroll
                for (int half = 0; half < 2; half++) {
                    int m = mbase + half*8;
                    int b_ = m >> 11, ns = m & (SEQ-1);
                    float vx = (c[mi][j][2*half+0] + bb.x) * scale;
                    float vy = (c[mi][j][2*half+1] + bb.y) * scale;
                    __nv_bfloat16 h0 = __float2bfloat16(vx);
                    __nv_bfloat16 h1 = __float2bfloat16(vy);
                    __nv_bfloat162 hi2; hi2.x = h0; hi2.y = h1;
                    __nv_bfloat162 lo2;
                    lo2.x = __float2bfloat16(vx - __bfloat162float(h0));
                    lo2.y = __float2bfloat16(vy - __bfloat162float(h1));
                    size_t qb = ((size_t)(b_*HEADS + h)*SEQ + ns)*KATT + d;
                    if (which == 0) {  // [Qh|Qh|Ql]
                        *(__nv_bfloat162*)&dc[qb      ] = hi2;
                        *(__nv_bfloat162*)&dc[qb + 64 ] = hi2;
                        *(__nv_bfloat162*)&dc[qb + 128] = lo2;
                    } else {           // [Kh|Kl|Kh]
                        *(__nv_bfloat162*)&dc[qb      ] = hi2;
                        *(__nv_bfloat162*)&dc[qb + 64 ] = lo2;
                        *(__nv_bfloat162*)&dc[qb + 128] = hi2;
                    }
                }
            }
        }
    }
}

// ---------------------------------------------------------------------------
// V (fp32 [hb][n][d]) -> transposed split-bf16 Vc[hb][tile][d][192 key-cat].
// ---------------------------------------------------------------------------
__global__ void convert_V()
{
    __shared__ float vt[64][68];   // 272B pitch: 16B-aligned float4 rows
    int hb = blockIdx.y, t0 = blockIdx.x;
    int tid = threadIdx.x;
    int key = tid >> 2, seg = (tid & 3) << 4;
    size_t rowg = ((size_t)hb*SEQ + t0*64 + key)*HDIM + seg;

    #pragma unroll
    for (int e = 0; e < 16; e += 4)
        *(float4*)&vt[key][seg+e] = *(const float4*)&g_v[rowg+e];
    __syncthreads();
    {
        int d = tid >> 2, kseg = (tid & 3) << 4;
        size_t ob = (((size_t)hb*32 + t0)*HDIM + d)*KATT + kseg;
        #pragma unroll
        for (int e = 0; e < 16; e += 2) {
            float v0 = vt[kseg+e  ][d];
            float v1 = vt[kseg+e+1][d];
            __nv_bfloat16 h0 = __float2bfloat16(v0), h1 = __float2bfloat16(v1);
            __nv_bfloat16 l0 = __float2bfloat16(v0 - __bfloat162float(h0));
            __nv_bfloat16 l1 = __float2bfloat16(v1 - __bfloat162float(h1));
            __nv_bfloat162 hi; hi.x = h0; hi.y = h1;
            __nv_bfloat162 lo; lo.x = l0; lo.y = l1;
            *(__nv_bfloat162*)&g_Vc[ob+e     ] = hi;
            *(__nv_bfloat162*)&g_Vc[ob+e+64  ] = lo;
            *(__nv_bfloat162*)&g_Vc[ob+e+128 ] = hi;
        }
    }
}

// ---------------------------------------------------------------------------
// Flash attention on HMMA. Block = (q-tile 128 rows, head); 8 warps (m16 each).
// 102.4 KB smem; K/V alternating cp.async pipeline; P stays in registers.
// grid (16, 32), 256 threads.
// ---------------------------------------------------------------------------
#define ROWB 400
#define QS_OFF 0
#define KS_OFF 51200
#define VS_OFF 76800
#define SMEM_ATT 102400

__device__ __forceinline__ void att_load_q(uint32_t dst, const char* src, int tid)
{
    #pragma unroll
    for (int r = 0; r < 12; r++) {          // 128 rows x 24 sectors
        int idx = tid + r*256;
        int row = idx / 24, sec = idx % 24;
        cp16(dst + row*ROWB + sec*16, src + row*384 + sec*16);
    }
}
__device__ __forceinline__ void att_load_kv(uint32_t dst, const char* src, int tid)
{
    #pragma unroll
    for (int r = 0; r < 6; r++) {           // 64 rows x 24 sectors
        int idx = tid + r*256;
        int row = idx / 24, sec = idx % 24;
        cp16(dst + row*ROWB + sec*16, src + row*384 + sec*16);
    }
}

__global__ __launch_bounds__(256) void attn_mma(float* __restrict__ out)
{
    extern __shared__ char smem[];
    uint32_t sb = smem_u32(smem);
    int tid = threadIdx.x, wid = tid >> 5, l = tid & 31;
    int hb = blockIdx.y, q0 = blockIdx.x * 128;

    const char* Qg = (const char*)(g_Qc + ((size_t)hb*SEQ + q0)*KATT);
    const char* Kg = (const char*)(g_Kc + (size_t)hb*SEQ*KATT);
    const char* Vg = (const char*)(g_Vc + (size_t)hb*32*HDIM*KATT);

    att_load_q(sb + QS_OFF, Qg, tid);
    att_load_kv(sb + KS_OFF, Kg, tid);
    CP_COMMIT();                         // group: {Q, K0}
    att_load_kv(sb + VS_OFF, Vg, tid);
    CP_COMMIT();                         // group: {V0}

    float o[8][4];
    #pragma unroll
    for (int j = 0; j < 8; j++)
        #pragma unroll
        for (int e = 0; e < 4; e++) o[j][e] = 0.f;
    float m0r = -1e30f, m1r = -1e30f, l0r = 0.f, l1r = 0.f;

    for (int i = 0; i < 32; i++) {
        CP_WAIT1();                      // K_i (and Q) ready
        __syncthreads();

        // ---- S = Qcat @ Kcat^T ----
        float s[8][4];
        #pragma unroll
        for (int j = 0; j < 8; j++)
            #pragma unroll
            for (int e = 0; e < 4; e++) s[j][e] = 0.f;

        #pragma unroll
        for (int kk = 0; kk < 12; kk++) {
            uint32_t a[4];
            {
                int row = wid*16 + (l & 15);
                int sec = 2*kk + (l >> 4);
                ldm4(a, sb + QS_OFF + row*ROWB + sec*16);
            }
            #pragma unroll
            for (int jp = 0; jp < 4; jp++) {
                uint32_t b[4];
                int row = jp*16 + (l & 7) + ((l >> 4) << 3);
                int sec = 2*kk + ((l >> 3) & 1);
                ldm4(b, sb + KS_OFF + row*ROWB + sec*16);
                mma16816(s[2*jp],   a, b[0], b[1]);
                mma16816(s[2*jp+1], a, b[2], b[3]);
            }
        }
        __syncthreads();                 // all warps done reading K_i
        if (i + 1 < 32) att_load_kv(sb + KS_OFF, Kg + (size_t)(i+1)*64*384, tid);
        CP_COMMIT();

        // ---- online softmax (rows: r=l/4 for e0/1, r+8 for e2/3) ----
        float rmax0 = -1e30f, rmax1 = -1e30f;
        #pragma unroll
        for (int j = 0; j < 8; j++) {
            rmax0 = fmaxf(rmax0, fmaxf(s[j][0], s[j][1]));
            rmax1 = fmaxf(rmax1, fmaxf(s[j][2], s[j][3]));
        }
        rmax0 = fmaxf(rmax0, __shfl_xor_sync(0xffffffffu, rmax0, 1));
        rmax0 = fmaxf(rmax0, __shfl_xor_sync(0xffffffffu, rmax0, 2));
        rmax1 = fmaxf(rmax1, __shfl_xor_sync(0xffffffffu, rmax1, 1));
        rmax1 = fmaxf(rmax1, __shfl_xor_sync(0xffffffffu, rmax1, 2));
        float nm0 = fmaxf(m0r, rmax0), nm1 = fmaxf(m1r, rmax1);
        float rs0 = 0.f, rs1 = 0.f;
        #pragma unroll
        for (int j = 0; j < 8; j++) {
            s[j][0] = __expf(s[j][0] - nm0);
            s[j][1] = __expf(s[j][1] - nm0);
            s[j][2] = __expf(s[j][2] - nm1);
            s[j][3] = __expf(s[j][3] - nm1);
            rs0 += s[j][0] + s[j][1];
            rs1 += s[j][2] + s[j][3];
        }
        rs0 += __shfl_xor_sync(0xffffffffu, rs0, 1);
        rs0 += __shfl_xor_sync(0xffffffffu, rs0, 2);
        rs1 += __shfl_xor_sync(0xffffffffu, rs1, 1);
        rs1 += __shfl_xor_sync(0xffffffffu, rs1, 2);
        float al0 = __expf(m0r - nm0), al1 = __expf(m1r - nm1);
        l0r = l0r*al0 + rs0;  l1r = l1r*al1 + rs1;
        m0r = nm0;  m1r = nm1;
        #pragma unroll
        for (int j = 0; j < 8; j++) {
            o[j][0] *= al0; o[j][1] *= al0;
            o[j][2] *= al1; o[j][3] *= al1;
        }

        // ---- pack P (hi + residual lo) into A fragments ----
        uint32_t ph[4][4], pl[4][4];
        #pragma unroll
        for (int kk = 0; kk < 4; kk++) {
            #pragma unroll
            for (int half = 0; half < 2; half++) {
                #pragma unroll
                for (int sub = 0; sub < 2; sub++) {
                    float p0 = s[2*kk+sub][2*half+0];
                    float p1 = s[2*kk+sub][2*half+1];
                    __nv_bfloat16 h0 = __float2bfloat16(p0);
                    __nv_bfloat16 h1 = __float2bfloat16(p1);
                    ph[kk][2*sub+half] = packbf2(h0, h1);
                    pl[kk][2*sub+half] = packbf2(
                        __float2bfloat16(p0 - __bfloat162float(h0)),
                        __float2bfloat16(p1 - __bfloat162float(h1)));
                }
            }
        }

        // ---- O += Pcat @ Vcat ----
        CP_WAIT1();                      // V_i ready
        __syncthreads();
        #pragma unroll
        for (int kb = 0; kb < 12; kb++) {
            const uint32_t* a = (kb < 4) ? ph[kb] : (kb < 8) ? ph[kb-4] : pl[kb-8];
            #pragma unroll
            for (int jp = 0; jp < 4; jp++) {
                uint32_t b[4];
                int row = jp*16 + (l & 7) + ((l >> 4) << 3);
                int sec = 2*kb + ((l >> 3) & 1);
                ldm4(b, sb + VS_OFF + row*ROWB + sec*16);
                mma16816(o[2*jp],   a, b[0], b[1]);
                mma16816(o[2*jp+1], a, b[2], b[3]);
            }
        }
        __syncthreads();                 // all warps done reading V_i
        if (i + 1 < 32) att_load_kv(sb + VS_OFF, Vg + (size_t)(i+1)*HDIM*384, tid);
        CP_COMMIT();
    }

    // ---- epilogue ----
    int b_ = hb >> 4, h = hb & 15;
    float inv0 = 1.f / l0r, inv1 = 1.f / l1r;
    int r0 = q0 + wid*16 + (l >> 2);
    #pragma unroll
    for (int j = 0; j < 8; j++) {
        int d = j*8 + (l & 3)*2;
        float2 v0; v0.x = o[j][0]*inv0; v0.y = o[j][1]*inv0;
        float2 v1; v1.x = o[j][2]*inv1; v1.y = o[j][3]*inv1;
        *(float2*)&out[((size_t)(b_*SEQ + r0  ))*EMBED + h*HDIM + d] = v0;
        *(float2*)&out[((size_t)(b_*SEQ + r0+8))*EMBED + h*HDIM + d] = v1;
    }
}

// ---------------------------------------------------------------------------
extern "C" void kernel_launch(void* const* d_in, const int* in_sizes, int n_in,
                              void* d_out, int out_size)
{
    const float* x  = (const float*)d_in[0];
    const float* Wq = (const float*)d_in[1];
    const float* bq = (const float*)d_in[2];
    const float* Wk = (const float*)d_in[3];
    const float* bk = (const float*)d_in[4];
    const float* Wv = (const float*)d_in[5];
    const float* bv = (const float*)d_in[6];
    const float* Wp = (const float*)d_in[7];
    float* out = (float*)d_out;

    cudaFuncSetAttribute(gemm_fused, cudaFuncAttributeMaxDynamicSharedMemorySize, SMEM_GEMM);
    cudaFuncSetAttribute(attn_mma,  cudaFuncAttributeMaxDynamicSharedMemorySize, SMEM_ATT);

    build_eff<<<dim3(EMBED+1, HEADS, 2), 64>>>(Wq, bq, Wk, bk, Wp);
    convert_X<<<8192, 256>>>(x);
    convert_W<<<dim3(32, 32, 3), dim3(32, 8)>>>(Wv);

    gemm_fused<<<dim3(MTOT/128, 24), 256, SMEM_GEMM>>>(bv);

    convert_V<<<dim3(32, 32), 256>>>();

    attn_mma<<<dim3(SEQ/128, BATCH*HEADS), 256, SMEM_ATT>>>(out);
}

// round 8
// speedup vs baseline: 1.0490x; 1.0490x over previous
#include <cuda_runtime.h>
#include <cuda_bf16.h>
#include <cstdint>
#include <math.h>

#define EMBED 1024
#define HEADS 16
#define HDIM  64
#define BATCH 2
#define SEQ   2048
#define MTOT  (BATCH*SEQ)   // 4096
#define KCAT  3072          // 3*EMBED (split-bf16 concat)
#define KATT  192           // 3*HDIM  (split concat for attention)

// ---------------- scratch (device globals; no allocation allowed) ----------
__device__ float g_WeffQ[EMBED*EMBED];
__device__ float g_WeffK[EMBED*EMBED];
__device__ float g_beffQ[EMBED];
__device__ float g_beffK[EMBED];
__device__ __align__(256) __nv_bfloat16 g_Xcat[MTOT*KCAT];      // [m][3072] = [Xh|Xh|Xl]
__device__ __align__(256) __nv_bfloat16 g_WcatQ[EMBED*KCAT];    // [n][3072] = [Wh|Wl|Wh]
__device__ __align__(256) __nv_bfloat16 g_WcatK[EMBED*KCAT];
__device__ __align__(256) __nv_bfloat16 g_WcatV[EMBED*KCAT];
__device__ float g_v[MTOT*EMBED];   // [hb][n][d]
__device__ __align__(256) __nv_bfloat16 g_Qc[32*SEQ*KATT];      // [hb][n][192] = [Qh|Qh|Ql]*0.125
__device__ __align__(256) __nv_bfloat16 g_Kc[32*SEQ*KATT];      // [hb][n][192] = [Kh|Kl|Kh]
__device__ __align__(256) __nv_bfloat16 g_Vc[32*32*HDIM*KATT];  // [hb][tile][d][192]=[Vh|Vl|Vh] keys

// ======================= PTX helpers (sm_80-level) =========================
__device__ __forceinline__ uint32_t smem_u32(const void* p) {
    uint32_t a;
    asm("{ .reg .u64 t; cvta.to.shared.u64 t, %1; cvt.u32.u64 %0, t; }" : "=r"(a) : "l"(p));
    return a;
}
__device__ __forceinline__ void cp16(uint32_t s, const void* g) {
    asm volatile("cp.async.cg.shared.global [%0], [%1], 16;" :: "r"(s), "l"(g));
}
#define CP_COMMIT() asm volatile("cp.async.commit_group;" ::: "memory")
#define CP_WAIT1()  asm volatile("cp.async.wait_group 1;" ::: "memory")
#define CP_WAIT0()  asm volatile("cp.async.wait_group 0;" ::: "memory")

__device__ __forceinline__ void mma16816(float* c, const uint32_t* a, uint32_t b0, uint32_t b1) {
    asm volatile("mma.sync.aligned.m16n8k16.row.col.f32.bf16.bf16.f32 "
        "{%0,%1,%2,%3}, {%4,%5,%6,%7}, {%8,%9}, {%0,%1,%2,%3};"
        : "+f"(c[0]), "+f"(c[1]), "+f"(c[2]), "+f"(c[3])
        : "r"(a[0]), "r"(a[1]), "r"(a[2]), "r"(a[3]), "r"(b0), "r"(b1));
}
__device__ __forceinline__ void ldm4(uint32_t* r, uint32_t addr) {
    asm volatile("ldmatrix.sync.aligned.m8n8.x4.shared.b16 {%0,%1,%2,%3}, [%4];"
        : "=r"(r[0]), "=r"(r[1]), "=r"(r[2]), "=r"(r[3]) : "r"(addr));
}
__device__ __forceinline__ uint32_t packbf2(__nv_bfloat16 lo, __nv_bfloat16 hi) {
    __nv_bfloat162 t; t.x = lo; t.y = hi;
    return *(uint32_t*)&t;
}

// ---------------------------------------------------------------------------
// Fold per-head Wp into Wq / Wk (and biases).
// ---------------------------------------------------------------------------
__global__ void build_eff(const float* __restrict__ Wq, const float* __restrict__ bq,
                          const float* __restrict__ Wk, const float* __restrict__ bk,
                          const float* __restrict__ Wp)
{
    __shared__ float WpS[64*64];
    int i = threadIdx.x;
    for (int t = i; t < 64*64; t += 64) WpS[t] = Wp[t];
    __syncthreads();

    int h = blockIdx.y;
    int e = blockIdx.x;
    const float* W    = blockIdx.z ? Wk      : Wq;
    const float* b    = blockIdx.z ? bk      : bq;
    float*       Weff = blockIdx.z ? g_WeffK : g_WeffQ;
    float*       beff = blockIdx.z ? g_beffK : g_beffQ;

    float acc = 0.f;
    if (e < EMBED) {
        const float* src = W + e*EMBED + h*HDIM;
        #pragma unroll 8
        for (int d = 0; d < 64; d++) acc = fmaf(src[d], WpS[d*64 + i], acc);
        Weff[e*EMBED + h*HDIM + i] = acc;
    } else {
        const float* src = b + h*HDIM;
        #pragma unroll 8
        for (int d = 0; d < 64; d++) acc = fmaf(src[d], WpS[d*64 + i], acc);
        beff[h*HDIM + i] = acc;
    }
}

// ---------------------------------------------------------------------------
// X -> split-bf16 K-concat:  Xcat[m] = [hi(X) | hi(X) | lo(X)]
// ---------------------------------------------------------------------------
__global__ void convert_X(const float* __restrict__ x)
{
    int t = blockIdx.x*256 + threadIdx.x;
    float2 v = ((const float2*)x)[t];
    int m = t >> 9;
    int e = (t & 511) << 1;
    __nv_bfloat16 hx = __float2bfloat16(v.x), hy = __float2bfloat16(v.y);
    __nv_bfloat16 lx = __float2bfloat16(v.x - __bfloat162float(hx));
    __nv_bfloat16 ly = __float2bfloat16(v.y - __bfloat162float(hy));
    __nv_bfloat162 hi; hi.x = hx; hi.y = hy;
    __nv_bfloat162 lo; lo.x = lx; lo.y = ly;
    size_t base = (size_t)m*KCAT + e;
    *(__nv_bfloat162*)&g_Xcat[base        ] = hi;
    *(__nv_bfloat162*)&g_Xcat[base + 1024 ] = hi;
    *(__nv_bfloat162*)&g_Xcat[base + 2048 ] = lo;
}

// ---------------------------------------------------------------------------
// W (fp32 [k][n]) -> transposed split-bf16:  Wcat[n] = [hi | lo | hi]
// ---------------------------------------------------------------------------
__global__ void convert_W(const float* __restrict__ Wv)
{
    __shared__ float tile[32][33];
    int z = blockIdx.z;
    const float* src = (z == 0) ? g_WeffQ : (z == 1) ? g_WeffK : Wv;
    __nv_bfloat16* dst = (z == 0) ? g_WcatQ : (z == 1) ? g_WcatK : g_WcatV;
    int k0 = blockIdx.y*32, n0 = blockIdx.x*32;
    int tx = threadIdx.x, ty = threadIdx.y;
    #pragma unroll
    for (int j = 0; j < 32; j += 8)
        tile[ty+j][tx] = src[(size_t)(k0+ty+j)*EMBED + n0 + tx];
    __syncthreads();
    #pragma unroll
    for (int j = 0; j < 32; j += 8) {
        int n = ty + j;
        float v = tile[tx][n];
        __nv_bfloat16 hi = __float2bfloat16(v);
        __nv_bfloat16 lo = __float2bfloat16(v - __bfloat162float(hi));
        size_t base = (size_t)(n0+n)*KCAT + k0 + tx;
        dst[base       ] = hi;
        dst[base + 1024] = lo;
        dst[base + 2048] = hi;
    }
}

// ---------------------------------------------------------------------------
// HMMA GEMM (round-6 proven core: 2-stage, 8 warps, 128x128, BK=64).
// which: 0=Q (split-bf16 out, scaled 1/8), 1=K (split-bf16), 2=V (fp32).
// ---------------------------------------------------------------------------
#define GSTAGE 32768
#define SMEM_GEMM (2*GSTAGE)
#define NCHUNK (KCAT/64)   // 48

__device__ __forceinline__ void gemm_load(const __nv_bfloat16* Bw,
                                          uint32_t sb, int stage, int m0, int n0,
                                          int chunk, int tid)
{
    uint32_t as = sb + stage*GSTAGE;
    uint32_t bs = as + 16384;
    const char* Ac = (const char*)g_Xcat;
    const char* Bc = (const char*)Bw;
    #pragma unroll
    for (int r = 0; r < 4; r++) {
        int idx = tid + r*256;
        int row = idx >> 3, sec = idx & 7;
        cp16(as + row*128 + (((sec ^ (row & 7))) << 4),
             Ac + ((size_t)(m0+row)*KCAT + chunk*64 + sec*8)*2);
    }
    #pragma unroll
    for (int r = 0; r < 4; r++) {
        int idx = tid + r*256;
        int row = idx >> 3, sec = idx & 7;
        cp16(bs + row*128 + (((sec ^ (row & 7))) << 4),
             Bc + ((size_t)(n0+row)*KCAT + chunk*64 + sec*8)*2);
    }
}

__global__ __launch_bounds__(256) void gemm_mma(
    const __nv_bfloat16* __restrict__ Bw,
    const float* __restrict__ bias, int which)
{
    extern __shared__ char smem[];
    uint32_t sb = smem_u32(smem);
    int tid = threadIdx.x, wid = tid >> 5, l = tid & 31;
    int m0 = blockIdx.x * 128, n0 = blockIdx.y * 128;
    int wm = (wid & 3) * 32, wn = (wid >> 2) * 64;

    float c[2][8][4];
    #pragma unroll
    for (int mi = 0; mi < 2; mi++)
        #pragma unroll
        for (int j = 0; j < 8; j++)
            #pragma unroll
            for (int e = 0; e < 4; e++) c[mi][j][e] = 0.f;

    gemm_load(Bw, sb, 0, m0, n0, 0, tid);
    CP_COMMIT();

    for (int i = 0; i < NCHUNK; i++) {
        if (i + 1 < NCHUNK) {
            gemm_load(Bw, sb, (i+1) & 1, m0, n0, i+1, tid);
            CP_COMMIT();
            CP_WAIT1();
        } else {
            CP_WAIT0();
        }
        __syncthreads();

        uint32_t as = sb + (i & 1)*GSTAGE;
        uint32_t bs = as + 16384;
        #pragma unroll
        for (int kk = 0; kk < 4; kk++) {
            uint32_t a0[4], a1[4];
            {
                int row = wm + (l & 15);
                int sec = 2*kk + (l >> 4);
                ldm4(a0, as + row*128 + ((sec ^ (row & 7)) << 4));
                row += 16;
                ldm4(a1, as + row*128 + ((sec ^ (row & 7)) << 4));
            }
            #pragma unroll
            for (int jp = 0; jp < 4; jp++) {
                uint32_t b[4];
                int row = wn + jp*16 + (l & 7) + ((l >> 4) << 3);
                int sec = 2*kk + ((l >> 3) & 1);
                ldm4(b, bs + row*128 + ((sec ^ (row & 7)) << 4));
                mma16816(c[0][2*jp],   a0, b[0], b[1]);
                mma16816(c[0][2*jp+1], a0, b[2], b[3]);
                mma16816(c[1][2*jp],   a1, b[0], b[1]);
                mma16816(c[1][2*jp+1], a1, b[2], b[3]);
            }
        }
        __syncthreads();
    }

    // ---- epilogue ----
    if (which == 2) {
        #pragma unroll
        for (int mi = 0; mi < 2; mi++) {
            int mbase = m0 + wm + mi*16 + (l >> 2);
            #pragma unroll
            for (int j = 0; j < 8; j++) {
                int ncol = n0 + wn + j*8 + (l & 3)*2;
                float2 bb = *(const float2*)&bias[ncol];
                int h = ncol >> 6, d = ncol & 63;
                #pragma unroll
                for (int half = 0; half < 2; half++) {
                    int m = mbase + half*8;
                    int b_ = m >> 11, ns = m & (SEQ-1);
                    float2 o;
                    o.x = c[mi][j][2*half+0] + bb.x;
                    o.y = c[mi][j][2*half+1] + bb.y;
                    *(float2*)&g_v[((size_t)(b_*HEADS + h)*SEQ + ns)*HDIM + d] = o;
                }
            }
        }
    } else {
        __nv_bfloat16* dc = (which == 0) ? g_Qc : g_Kc;
        float scale = (which == 0) ? 0.125f : 1.0f;
        #pragma unroll
        for (int mi = 0; mi < 2; mi++) {
            int mbase = m0 + wm + mi*16 + (l >> 2);
            #pragma unroll
            for (int j = 0; j < 8; j++) {
                int ncol = n0 + wn + j*8 + (l & 3)*2;
                float2 bb = *(const float2*)&bias[ncol];
                int h = ncol >> 6, d = ncol & 63;
                #pragma unroll
                for (int half = 0; half < 2; half++) {
                    int m = mbase + half*8;
                    int b_ = m >> 11, ns = m & (SEQ-1);
                    float vx = (c[mi][j][2*half+0] + bb.x) * scale;
                    float vy = (c[mi][j][2*half+1] + bb.y) * scale;
                    __nv_bfloat16 h0 = __float2bfloat16(vx);
                    __nv_bfloat16 h1 = __float2bfloat16(vy);
                    __nv_bfloat162 hi2; hi2.x = h0; hi2.y = h1;
                    __nv_bfloat162 lo2;
                    lo2.x = __float2bfloat16(vx - __bfloat162float(h0));
                    lo2.y = __float2bfloat16(vy - __bfloat162float(h1));
                    size_t qb = ((size_t)(b_*HEADS + h)*SEQ + ns)*KATT + d;
                    if (which == 0) {  // [Qh|Qh|Ql]
                        *(__nv_bfloat162*)&dc[qb      ] = hi2;
                        *(__nv_bfloat162*)&dc[qb + 64 ] = hi2;
                        *(__nv_bfloat162*)&dc[qb + 128] = lo2;
                    } else {           // [Kh|Kl|Kh]
                        *(__nv_bfloat162*)&dc[qb      ] = hi2;
                        *(__nv_bfloat162*)&dc[qb + 64 ] = lo2;
                        *(__nv_bfloat162*)&dc[qb + 128] = hi2;
                    }
                }
            }
        }
    }
}

// ---------------------------------------------------------------------------
// V (fp32 [hb][n][d]) -> transposed split-bf16 Vc[hb][tile][d][192 key-cat].
// ---------------------------------------------------------------------------
__global__ void convert_V()
{
    __shared__ float vt[64][68];   // 272B pitch: 16B-aligned float4 rows
    int hb = blockIdx.y, t0 = blockIdx.x;
    int tid = threadIdx.x;
    int key = tid >> 2, seg = (tid & 3) << 4;
    size_t rowg = ((size_t)hb*SEQ + t0*64 + key)*HDIM + seg;

    #pragma unroll
    for (int e = 0; e < 16; e += 4)
        *(float4*)&vt[key][seg+e] = *(const float4*)&g_v[rowg+e];
    __syncthreads();
    {
        int d = tid >> 2, kseg = (tid & 3) << 4;
        size_t ob = (((size_t)hb*32 + t0)*HDIM + d)*KATT + kseg;
        #pragma unroll
        for (int e = 0; e < 16; e += 2) {
            float v0 = vt[kseg+e  ][d];
            float v1 = vt[kseg+e+1][d];
            __nv_bfloat16 h0 = __float2bfloat16(v0), h1 = __float2bfloat16(v1);
            __nv_bfloat16 l0 = __float2bfloat16(v0 - __bfloat162float(h0));
            __nv_bfloat16 l1 = __float2bfloat16(v1 - __bfloat162float(h1));
            __nv_bfloat162 hi; hi.x = h0; hi.y = h1;
            __nv_bfloat162 lo; lo.x = l0; lo.y = l1;
            *(__nv_bfloat162*)&g_Vc[ob+e     ] = hi;
            *(__nv_bfloat162*)&g_Vc[ob+e+64  ] = lo;
            *(__nv_bfloat162*)&g_Vc[ob+e+128 ] = hi;
        }
    }
}

// ---------------------------------------------------------------------------
// Flash attention on HMMA. 64 q-rows, 4 warps, Q fragments in REGISTERS,
// K and V double-buffered (2 syncs/iter, prefetch before compute).
// smem: KB0,KB1,VB0,VB1 of 25.6KB each = 102.4KB -> 2 CTAs/SM.
// grid (32, 32), 128 threads.
// ---------------------------------------------------------------------------
#define ROWB 400
#define KB0 0
#define KB1 25600
#define VB0 51200
#define VB1 76800
#define SMEM_ATT 102400

__device__ __forceinline__ void att_load_kv(uint32_t dst, const char* src, int tid)
{
    #pragma unroll
    for (int r = 0; r < 12; r++) {          // 64 rows x 24 sectors
        int idx = tid + r*128;
        int row = idx / 24, sec = idx % 24;
        cp16(dst + row*ROWB + sec*16, src + row*384 + sec*16);
    }
}

__global__ __launch_bounds__(128) void attn_mma(float* __restrict__ out)
{
    extern __shared__ char smem[];
    uint32_t sb = smem_u32(smem);
    int tid = threadIdx.x, wid = tid >> 5, l = tid & 31;
    int hb = blockIdx.y, q0 = blockIdx.x * 64;

    const char* Qg = (const char*)(g_Qc + ((size_t)hb*SEQ + q0)*KATT);
    const char* Kg = (const char*)(g_Kc + (size_t)hb*SEQ*KATT);
    const char* Vg = (const char*)(g_Vc + (size_t)hb*32*HDIM*KATT);

    // startup: Q->VB1 + K0->KB0 (group 1);  V0->VB0 (group 2)
    att_load_kv(sb + VB1, Qg, tid);
    att_load_kv(sb + KB0, Kg, tid);
    CP_COMMIT();
    att_load_kv(sb + VB0, Vg, tid);
    CP_COMMIT();

    CP_WAIT1();                          // Q + K0 ready
    __syncthreads();

    // Q fragments -> registers (loop-invariant)
    uint32_t qf[12][4];
    #pragma unroll
    for (int kk = 0; kk < 12; kk++) {
        int row = wid*16 + (l & 15);
        int sec = 2*kk + (l >> 4);
        ldm4(qf[kk], sb + VB1 + row*ROWB + sec*16);
    }

    float o[8][4];
    #pragma unroll
    for (int j = 0; j < 8; j++)
        #pragma unroll
        for (int e = 0; e < 4; e++) o[j][e] = 0.f;
    float m0r = -1e30f, m1r = -1e30f, l0r = 0.f, l1r = 0.f;

    for (int i = 0; i < 32; i++) {
        CP_WAIT1();                      // K_i complete (V_i may pend)
        __syncthreads();
        if (i + 1 < 32) {                // prefetch K_{i+1} into other buffer
            att_load_kv(sb + (((i+1) & 1) ? KB1 : KB0),
                        Kg + (size_t)(i+1)*64*384, tid);
            CP_COMMIT();
        }
        uint32_t kbase = sb + ((i & 1) ? KB1 : KB0);

        // ---- S = Qcat @ Kcat^T ----
        float s[8][4];
        #pragma unroll
        for (int j = 0; j < 8; j++)
            #pragma unroll
            for (int e = 0; e < 4; e++) s[j][e] = 0.f;

        #pragma unroll
        for (int kk = 0; kk < 12; kk++) {
            #pragma unroll
            for (int jp = 0; jp < 4; jp++) {
                uint32_t b[4];
                int row = jp*16 + (l & 7) + ((l >> 4) << 3);
                int sec = 2*kk + ((l >> 3) & 1);
                ldm4(b, kbase + row*ROWB + sec*16);
                mma16816(s[2*jp],   qf[kk], b[0], b[1]);
                mma16816(s[2*jp+1], qf[kk], b[2], b[3]);
            }
        }

        // ---- online softmax ----
        float rmax0 = -1e30f, rmax1 = -1e30f;
        #pragma unroll
        for (int j = 0; j < 8; j++) {
            rmax0 = fmaxf(rmax0, fmaxf(s[j][0], s[j][1]));
            rmax1 = fmaxf(rmax1, fmaxf(s[j][2], s[j][3]));
        }
        rmax0 = fmaxf(rmax0, __shfl_xor_sync(0xffffffffu, rmax0, 1));
        rmax0 = fmaxf(rmax0, __shfl_xor_sync(0xffffffffu, rmax0, 2));
        rmax1 = fmaxf(rmax1, __shfl_xor_sync(0xffffffffu, rmax1, 1));
        rmax1 = fmaxf(rmax1, __shfl_xor_sync(0xffffffffu, rmax1, 2));
        float nm0 = fmaxf(m0r, rmax0), nm1 = fmaxf(m1r, rmax1);
        float rs0 = 0.f, rs1 = 0.f;
        #pragma unroll
        for (int j = 0; j < 8; j++) {
            s[j][0] = __expf(s[j][0] - nm0);
            s[j][1] = __expf(s[j][1] - nm0);
            s[j][2] = __expf(s[j][2] - nm1);
            s[j][3] = __expf(s[j][3] - nm1);
            rs0 += s[j][0] + s[j][1];
            rs1 += s[j][2] + s[j][3];
        }
        rs0 += __shfl_xor_sync(0xffffffffu, rs0, 1);
        rs0 += __shfl_xor_sync(0xffffffffu, rs0, 2);
        rs1 += __shfl_xor_sync(0xffffffffu, rs1, 1);
        rs1 += __shfl_xor_sync(0xffffffffu, rs1, 2);
        float al0 = __expf(m0r - nm0), al1 = __expf(m1r - nm1);
        l0r = l0r*al0 + rs0;  l1r = l1r*al1 + rs1;
        m0r = nm0;  m1r = nm1;
        #pragma unroll
        for (int j = 0; j < 8; j++) {
            o[j][0] *= al0; o[j][1] *= al0;
            o[j][2] *= al1; o[j][3] *= al1;
        }

        // ---- pack P (hi + residual lo) into A fragments ----
        uint32_t ph[4][4], pl[4][4];
        #pragma unroll
        for (int kk = 0; kk < 4; kk++) {
            #pragma unroll
            for (int half = 0; half < 2; half++) {
                #pragma unroll
                for (int sub = 0; sub < 2; sub++) {
                    float p0 = s[2*kk+sub][2*half+0];
                    float p1 = s[2*kk+sub][2*half+1];
                    __nv_bfloat16 h0 = __float2bfloat16(p0);
                    __nv_bfloat16 h1 = __float2bfloat16(p1);
                    ph[kk][2*sub+half] = packbf2(h0, h1);
                    pl[kk][2*sub+half] = packbf2(
                        __float2bfloat16(p0 - __bfloat162float(h0)),
                        __float2bfloat16(p1 - __bfloat162float(h1)));
                }
            }
        }

        // ---- O += Pcat @ Vcat ----
        if (i + 1 < 32) { CP_WAIT1(); } else { CP_WAIT0(); }   // V_i complete
        __syncthreads();
        if (i + 1 < 32) {                // prefetch V_{i+1} into other buffer
            att_load_kv(sb + (((i+1) & 1) ? VB1 : VB0),
                        Vg + (size_t)(i+1)*HDIM*384, tid);
            CP_COMMIT();
        }
        uint32_t vbase = sb + ((i & 1) ? VB1 : VB0);
        #pragma unroll
        for (int kb = 0; kb < 12; kb++) {
            const uint32_t* a = (kb < 4) ? ph[kb] : (kb < 8) ? ph[kb-4] : pl[kb-8];
            #pragma unroll
            for (int jp = 0; jp < 4; jp++) {
                uint32_t b[4];
                int row = jp*16 + (l & 7) + ((l >> 4) << 3);
                int sec = 2*kb + ((l >> 3) & 1);
                ldm4(b, vbase + row*ROWB + sec*16);
                mma16816(o[2*jp],   a, b[0], b[1]);
                mma16816(o[2*jp+1], a, b[2], b[3]);
            }
        }
    }

    // ---- epilogue ----
    int b_ = hb >> 4, h = hb & 15;
    float inv0 = 1.f / l0r, inv1 = 1.f / l1r;
    int r0 = q0 + wid*16 + (l >> 2);
    #pragma unroll
    for (int j = 0; j < 8; j++) {
        int d = j*8 + (l & 3)*2;
        float2 v0; v0.x = o[j][0]*inv0; v0.y = o[j][1]*inv0;
        float2 v1; v1.x = o[j][2]*inv1; v1.y = o[j][3]*inv1;
        *(float2*)&out[((size_t)(b_*SEQ + r0  ))*EMBED + h*HDIM + d] = v0;
        *(float2*)&out[((size_t)(b_*SEQ + r0+8))*EMBED + h*HDIM + d] = v1;
    }
}

// ---------------------------------------------------------------------------
extern "C" void kernel_launch(void* const* d_in, const int* in_sizes, int n_in,
                              void* d_out, int out_size)
{
    const float* x  = (const float*)d_in[0];
    const float* Wq = (const float*)d_in[1];
    const float* bq = (const float*)d_in[2];
    const float* Wk = (const float*)d_in[3];
    const float* bk = (const float*)d_in[4];
    const float* Wv = (const float*)d_in[5];
    const float* bv = (const float*)d_in[6];
    const float* Wp = (const float*)d_in[7];
    float* out = (float*)d_out;

    cudaFuncSetAttribute(gemm_mma, cudaFuncAttributeMaxDynamicSharedMemorySize, SMEM_GEMM);
    cudaFuncSetAttribute(attn_mma, cudaFuncAttributeMaxDynamicSharedMemorySize, SMEM_ATT);

    float *pbeffQ, *pbeffK;
    __nv_bfloat16 *pWcatQ, *pWcatK, *pWcatV;
    cudaGetSymbolAddress((void**)&pbeffQ, g_beffQ);
    cudaGetSymbolAddress((void**)&pbeffK, g_beffK);
    cudaGetSymbolAddress((void**)&pWcatQ, g_WcatQ);
    cudaGetSymbolAddress((void**)&pWcatK, g_WcatK);
    cudaGetSymbolAddress((void**)&pWcatV, g_WcatV);

    build_eff<<<dim3(EMBED+1, HEADS, 2), 64>>>(Wq, bq, Wk, bk, Wp);
    convert_X<<<8192, 256>>>(x);
    convert_W<<<dim3(32, 32, 3), dim3(32, 8)>>>(Wv);

    gemm_mma<<<dim3(MTOT/128, EMBED/128), 256, SMEM_GEMM>>>(pWcatQ, pbeffQ, 0);
    gemm_mma<<<dim3(MTOT/128, EMBED/128), 256, SMEM_GEMM>>>(pWcatK, pbeffK, 1);
    gemm_mma<<<dim3(MTOT/128, EMBED/128), 256, SMEM_GEMM>>>(pWcatV, bv,     2);

    convert_V<<<dim3(32, 32), 256>>>();

    attn_mma<<<dim3(SEQ/64, BATCH*HEADS), 128, SMEM_ATT>>>(out);
}